// round 11
// baseline (speedup 1.0000x reference)
#include <cuda_runtime.h>
#include <cuda_bf16.h>
#include <cstdint>

#define S_LEN 32768
#define HDIM  1024
#define H3    3072
#define BM    64                   // s-rows per CTA
#define BN    64                   // i-cols per pass
#define NPASS 16
#define KCH   64                   // k elements per chunk (128 B bf16 row)
#define CH_PER_PASS (HDIM / KCH)   // 16
#define NCHUNKS (NPASS * CH_PER_PASS)    // 256
#define GRID_MAIN (S_LEN / BM)     // 512
#define NTHR  128

// Warp-private SMEM region: [A s0 4K][A s1 4K][B s0 4K][B s1 4K] = 16 KB
#define WREG   16384
#define SM_RED (4 * WREG)                    // 65536 (128 floats)
#define SM_SR  (SM_RED + 512)                // 66048
#define SMEM_TOTAL (SM_SR + 16)              // 66064 (x3 CTA/SM = 198 KB)

__device__ float g_c[HDIM];
__device__ float g_part[GRID_MAIN];
__device__ __align__(16) __nv_bfloat16 g_encb[(size_t)S_LEN * HDIM]; // 64 MB
__device__ __align__(16) __nv_bfloat16 g_wb[HDIM * HDIM];            // 2 MB

// ---------------- helpers ----------------
__device__ __forceinline__ unsigned smem_u32(const void* p) {
    return (unsigned)__cvta_generic_to_shared(p);
}
__device__ __forceinline__ float fast_tanh(float x) {
    float e, r;
    asm("ex2.approx.f32 %0, %1;" : "=f"(e) : "f"(x * 2.885390082f));
    asm("rcp.approx.f32 %0, %1;" : "=f"(r) : "f"(e + 1.0f));
    return fmaf(-2.0f, r, 1.0f);
}
__device__ __forceinline__ void mma16(float* d, const uint32_t* a,
                                      uint32_t b0, uint32_t b1) {
    asm volatile(
        "mma.sync.aligned.m16n8k16.row.col.f32.bf16.bf16.f32 "
        "{%0,%1,%2,%3}, {%4,%5,%6,%7}, {%8,%9}, {%0,%1,%2,%3};"
        : "+f"(d[0]), "+f"(d[1]), "+f"(d[2]), "+f"(d[3])
        : "r"(a[0]), "r"(a[1]), "r"(a[2]), "r"(a[3]), "r"(b0), "r"(b1));
}
__device__ __forceinline__ void ldsm4(uint32_t* d, unsigned addr) {
    asm volatile(
        "ldmatrix.sync.aligned.m8n8.x4.shared.b16 {%0,%1,%2,%3}, [%4];"
        : "=r"(d[0]), "=r"(d[1]), "=r"(d[2]), "=r"(d[3]) : "r"(addr));
}

// Warp-private chunk load: A 32x64 bf16 + B 32x64 bf16 (this warp's tiles).
__device__ __forceinline__ void load_chunk_w(unsigned wb, int stage, int gc,
                                             const __nv_bfloat16* __restrict__ aG,
                                             const __nv_bfloat16* __restrict__ bG,
                                             int lane) {
    const int kt = (gc & (CH_PER_PASS - 1)) * KCH;
    const int i0 = (gc / CH_PER_PASS) * BN;
    const unsigned ab = wb + stage * 4096;
    const unsigned bb = wb + 8192 + stage * 4096;
    const int rb = lane >> 3;      // 0..3 (+4 per j)
    const int q  = lane & 7;
    #pragma unroll
    for (int j = 0; j < 8; j++) {              // A rows rb+4j
        int r = rb + j * 4;
        unsigned dst = ab + (unsigned)(r * 128 + ((q ^ (r & 7)) * 16));
        const __nv_bfloat16* src = aG + (size_t)r * HDIM + kt + q * 8;
        asm volatile("cp.async.cg.shared.global [%0], [%1], 16;"
                     :: "r"(dst), "l"(src) : "memory");
    }
    #pragma unroll
    for (int j = 0; j < 8; j++) {              // B rows rb+4j (i = i0 + local)
        int r = rb + j * 4;
        unsigned dst = bb + (unsigned)(r * 128 + ((q ^ (r & 7)) * 16));
        const __nv_bfloat16* src = bG + (size_t)(i0 + r) * HDIM + kt + q * 8;
        asm volatile("cp.async.cg.shared.global [%0], [%1], 16;"
                     :: "r"(dst), "l"(src) : "memory");
    }
    asm volatile("cp.async.commit_group;" ::: "memory");
}

// ---------------------------------------------------------------------------
// Convert kernels (fp32 -> bf16, RTN)
// ---------------------------------------------------------------------------
__global__ void convert_enc_kernel(const float* __restrict__ enc) {
    size_t gid = (size_t)blockIdx.x * blockDim.x + threadIdx.x;
    size_t base = gid * 8;
    float4 a = *(const float4*)(enc + base);
    float4 b = *(const float4*)(enc + base + 4);
    __nv_bfloat162 r[4];
    r[0] = __floats2bfloat162_rn(a.x, a.y);
    r[1] = __floats2bfloat162_rn(a.z, a.w);
    r[2] = __floats2bfloat162_rn(b.x, b.y);
    r[3] = __floats2bfloat162_rn(b.z, b.w);
    *(uint4*)(g_encb + base) = *(uint4*)r;
}
__global__ void convert_w_kernel(const float* __restrict__ attn_w) {
    size_t gid = (size_t)blockIdx.x * blockDim.x + threadIdx.x;
    size_t base = gid * 8;
    size_t i = base >> 10, k = base & 1023;
    const float* src = attn_w + i * H3 + 2 * HDIM + k;
    float4 a = *(const float4*)src;
    float4 b = *(const float4*)(src + 4);
    __nv_bfloat162 r[4];
    r[0] = __floats2bfloat162_rn(a.x, a.y);
    r[1] = __floats2bfloat162_rn(a.z, a.w);
    r[2] = __floats2bfloat162_rn(b.x, b.y);
    r[3] = __floats2bfloat162_rn(b.z, b.w);
    *(uint4*)(g_wb + base) = *(uint4*)r;
}

// ---------------------------------------------------------------------------
// Kernel 1: c[i] = hidden . attn_w[i, 0:2H] + attn_b[i]   (fp32)
// ---------------------------------------------------------------------------
__global__ void precompute_c_kernel(const float* __restrict__ hidden,
                                    const float* __restrict__ attn_w,
                                    const float* __restrict__ attn_b) {
    int warp = (blockIdx.x * blockDim.x + threadIdx.x) >> 5;
    int lane = threadIdx.x & 31;
    if (warp >= HDIM) return;
    const float* wrow = attn_w + (size_t)warp * H3;
    float s = 0.f;
    #pragma unroll 8
    for (int j = lane; j < 2 * HDIM; j += 32)
        s += hidden[j] * wrow[j];
    #pragma unroll
    for (int off = 16; off; off >>= 1)
        s += __shfl_down_sync(0xffffffffu, s, off);
    if (lane == 0) g_c[warp] = s + attn_b[warp];
}

// ---------------------------------------------------------------------------
// Kernel 2: bf16 m16n8k16 GEMM, warp-private staging, ZERO mainloop barriers.
//   4 warps = 2(M) x 2(N).  Warp tile 32x32.  acc = 32 regs.
//   Each warp cp.asyncs its own A/B tiles and waits only on itself.
// ---------------------------------------------------------------------------
__global__ __launch_bounds__(NTHR, 3)
void attn_main_kernel(const float* __restrict__ v_w, float* __restrict__ out) {
    extern __shared__ char smem[];
    const unsigned sb = smem_u32(smem);
    const int tid  = threadIdx.x;
    const int wid  = tid >> 5;
    const int lane = tid & 31;
    const int g    = lane >> 2;        // 0..7
    const int c    = lane & 3;         // 0..3
    const int m0   = (wid & 1) * 32;   // 2 M-warps
    const int nOff = (wid >> 1) * 32;  // 2 N-warps
    const int s0   = blockIdx.x * BM;

    float* red = (float*)(smem + SM_RED);
    float* sr  = (float*)(smem + SM_SR);

    const unsigned wb = sb + wid * WREG;
    const __nv_bfloat16* aG = g_encb + (size_t)(s0 + m0) * HDIM;
    const __nv_bfloat16* bG = g_wb + (size_t)nOff * HDIM;

    // ldmatrix lane geometry within the warp-private 32-row tiles
    const int arow = ((lane >> 3) & 1) * 8 + (lane & 7);   // + mt*16
    const int aswz = arow & 7;
    const int acol = lane >> 4;                            // k half
    const int brow = (lane >> 4) * 8 + (lane & 7);         // + p*16
    const int bswz = brow & 7;
    const int bcol = (lane >> 3) & 1;                      // k half

    // prologue: chunk 0 into private stage 0
    load_chunk_w(wb, 0, 0, aG, bG, lane);

    float acc[2][4][4];
    float part[4] = {0.f, 0.f, 0.f, 0.f};

    for (int gc = 0; gc < NCHUNKS; gc++) {
        const int cur = gc & 1;

        if (gc + 1 < NCHUNKS) {
            load_chunk_w(wb, cur ^ 1, gc + 1, aG, bG, lane);
            asm volatile("cp.async.wait_group 1;" ::: "memory");
        } else {
            asm volatile("cp.async.wait_group 0;" ::: "memory");
        }

        if ((gc & (CH_PER_PASS - 1)) == 0) {
            #pragma unroll
            for (int mt = 0; mt < 2; mt++)
                #pragma unroll
                for (int nt = 0; nt < 4; nt++)
                    #pragma unroll
                    for (int q = 0; q < 4; q++) acc[mt][nt][q] = 0.f;
        }

        const unsigned aS = wb + cur * 4096;
        const unsigned bS = wb + 8192 + cur * 4096;

        #pragma unroll
        for (int ks = 0; ks < 4; ks++) {       // four k16 steps cover KCH=64
            uint32_t af[2][4], bf[2][4];
            const int aq = ((ks * 2 + acol) ^ aswz) * 16;
            const int bq = ((ks * 2 + bcol) ^ bswz) * 16;
            #pragma unroll
            for (int mt = 0; mt < 2; mt++)
                ldsm4(af[mt], aS + (unsigned)((arow + mt * 16) * 128 + aq));
            #pragma unroll
            for (int p = 0; p < 2; p++)
                ldsm4(bf[p], bS + (unsigned)((brow + p * 16) * 128 + bq));
            #pragma unroll
            for (int p = 0; p < 2; p++) {
                #pragma unroll
                for (int mt = 0; mt < 2; mt++) {
                    mma16(acc[mt][2 * p + 0], af[mt], bf[p][0], bf[p][1]);
                    mma16(acc[mt][2 * p + 1], af[mt], bf[p][2], bf[p][3]);
                }
            }
        }

        // per-pass fused epilogue: tanh + v-dot into register partials
        if ((gc & (CH_PER_PASS - 1)) == CH_PER_PASS - 1) {
            const int pass = gc / CH_PER_PASS;
            #pragma unroll
            for (int mt = 0; mt < 2; mt++) {
                #pragma unroll
                for (int nt = 0; nt < 4; nt++) {
                    int i = pass * BN + nOff + nt * 8 + c * 2;
                    float2 cv = __ldg((const float2*)(g_c + i));
                    float2 vv = __ldg((const float2*)(v_w + i));
                    part[mt*2+0] = fmaf(vv.x, fast_tanh(acc[mt][nt][0] + cv.x),
                                   fmaf(vv.y, fast_tanh(acc[mt][nt][1] + cv.y),
                                        part[mt*2+0]));
                    part[mt*2+1] = fmaf(vv.x, fast_tanh(acc[mt][nt][2] + cv.x),
                                   fmaf(vv.y, fast_tanh(acc[mt][nt][3] + cv.y),
                                        part[mt*2+1]));
                }
            }
        }
    }

    // reduce the 4 quad lanes (same rows, different col pairs)
    #pragma unroll
    for (int r = 0; r < 4; r++) {
        part[r] += __shfl_xor_sync(0xffffffffu, part[r], 1);
        part[r] += __shfl_xor_sync(0xffffffffu, part[r], 2);
    }
    if (c == 0) {
        const int nw = wid >> 1;
        #pragma unroll
        for (int mt = 0; mt < 2; mt++) {
            #pragma unroll
            for (int h = 0; h < 2; h++) {
                int row = m0 + mt * 16 + h * 8 + g;
                red[nw * 64 + row] = part[mt * 2 + h];
            }
        }
    }
    __syncthreads();                           // only barrier in the kernel

    float ex = 0.f;
    if (tid < BM) {
        float logit = red[tid] + red[64 + tid];   // |logit| <= ~26
        ex = expf(logit);
        out[s0 + tid] = ex;
    }
    #pragma unroll
    for (int off = 16; off; off >>= 1)
        ex += __shfl_down_sync(0xffffffffu, ex, off);
    if (lane == 0 && wid < 2) sr[wid] = ex;
    __syncthreads();
    if (tid == 0)
        g_part[blockIdx.x] = sr[0] + sr[1];
}

// ---------------------------------------------------------------------------
// Kernel 3: finalize — every block redundantly tree-reduces the 512 block
// partials (deterministic), then normalizes its slice of out.
// ---------------------------------------------------------------------------
__global__ void finalize_kernel(float* __restrict__ out) {
    __shared__ float sm[256];
    int t = threadIdx.x;
    sm[t] = g_part[t] + g_part[t + 256];
    __syncthreads();
    #pragma unroll
    for (int o = 128; o > 0; o >>= 1) {
        if (t < o) sm[t] += sm[t + o];
        __syncthreads();
    }
    float inv = 1.f / sm[0];
    int i = blockIdx.x * 256 + t;
    out[i] *= inv;
}

// ---------------------------------------------------------------------------
extern "C" void kernel_launch(void* const* d_in, const int* in_sizes, int n_in,
                              void* d_out, int out_size) {
    const float* hidden = (const float*)d_in[0];
    const float* enc    = (const float*)d_in[1];
    const float* attn_w = (const float*)d_in[2];
    const float* attn_b = (const float*)d_in[3];
    const float* v_w    = (const float*)d_in[4];
    float* out = (float*)d_out;

    cudaFuncSetAttribute(attn_main_kernel,
                         cudaFuncAttributeMaxDynamicSharedMemorySize, SMEM_TOTAL);

    convert_enc_kernel<<<16384, 256>>>(enc);
    convert_w_kernel<<<512, 256>>>(attn_w);
    precompute_c_kernel<<<128, 256>>>(hidden, attn_w, attn_b);
    attn_main_kernel<<<GRID_MAIN, NTHR, SMEM_TOTAL>>>(v_w, out);
    finalize_kernel<<<S_LEN / 256, 256>>>(out);
}

// round 12
// speedup vs baseline: 1.1486x; 1.1486x over previous
#include <cuda_runtime.h>
#include <cuda_bf16.h>
#include <cstdint>

#define S_LEN 32768
#define HDIM  1024
#define H3    3072
#define BM    128                 // s-rows per CTA
#define BN    128                 // i-cols per pass
#define NPASS 8
#define KCH   64                  // k elements per chunk (128 B bf16 row)
#define CH_PER_PASS (HDIM / KCH)  // 16
#define NCHUNKS (NPASS * CH_PER_PASS)   // 128
#define GRID_MAIN (S_LEN / BM)    // 256
#define NTHR  128
#define NSTAGE 3

// SMEM (bytes). Rows exactly 128 B, XOR-swizzled (SW128).
#define STG    16384              // 128 rows * 128 B
#define SM_A   0                  // 3 stages
#define SM_B   (NSTAGE * STG)                // 49152, 3 stages
#define SM_RED (SM_B + NSTAGE * STG)         // 98304 (256 floats)
#define SM_SR  (SM_RED + 1024)               // 99328
#define SMEM_TOTAL (SM_SR + 16)              // 99344 (x2 CTA/SM = 199 KB)

__device__ float g_c[HDIM];
__device__ float g_part[GRID_MAIN];
__device__ __align__(16) __nv_bfloat16 g_encb[(size_t)S_LEN * HDIM]; // 64 MB
__device__ __align__(16) __nv_bfloat16 g_wb[HDIM * HDIM];            // 2 MB

// ---------------- helpers ----------------
__device__ __forceinline__ unsigned smem_u32(const void* p) {
    return (unsigned)__cvta_generic_to_shared(p);
}
__device__ __forceinline__ float fast_tanh(float x) {
    float e, r;
    asm("ex2.approx.f32 %0, %1;" : "=f"(e) : "f"(x * 2.885390082f));
    asm("rcp.approx.f32 %0, %1;" : "=f"(r) : "f"(e + 1.0f));
    return fmaf(-2.0f, r, 1.0f);
}
__device__ __forceinline__ void mma16(float* d, const uint32_t* a,
                                      uint32_t b0, uint32_t b1) {
    asm volatile(
        "mma.sync.aligned.m16n8k16.row.col.f32.bf16.bf16.f32 "
        "{%0,%1,%2,%3}, {%4,%5,%6,%7}, {%8,%9}, {%0,%1,%2,%3};"
        : "+f"(d[0]), "+f"(d[1]), "+f"(d[2]), "+f"(d[3])
        : "r"(a[0]), "r"(a[1]), "r"(a[2]), "r"(a[3]), "r"(b0), "r"(b1));
}
__device__ __forceinline__ void ldsm4(uint32_t* d, unsigned addr) {
    asm volatile(
        "ldmatrix.sync.aligned.m8n8.x4.shared.b16 {%0,%1,%2,%3}, [%4];"
        : "=r"(d[0]), "=r"(d[1]), "=r"(d[2]), "=r"(d[3]) : "r"(addr));
}

// cp.async one chunk: A 128x64 bf16, B 128x64 bf16, SW128 XOR swizzle
__device__ __forceinline__ void load_chunk(unsigned sb, int stage, int gc,
                                           int s0, int tid) {
    const int kt = (gc & (CH_PER_PASS - 1)) * KCH;
    const int i0 = (gc / CH_PER_PASS) * BN;
    const unsigned ab = sb + SM_A + stage * STG;
    const unsigned bb = sb + SM_B + stage * STG;
    #pragma unroll
    for (int j = 0; j < 8; j++) {              // A: 1024 x 16B
        int idx = tid + j * NTHR;
        int row = idx >> 3, q = idx & 7;
        unsigned dst = ab + (unsigned)(row * 128 + ((q ^ (row & 7)) * 16));
        const __nv_bfloat16* src = g_encb + (size_t)(s0 + row) * HDIM + kt + q * 8;
        asm volatile("cp.async.cg.shared.global [%0], [%1], 16;"
                     :: "r"(dst), "l"(src) : "memory");
    }
    #pragma unroll
    for (int j = 0; j < 8; j++) {              // B: 1024 x 16B
        int idx = tid + j * NTHR;
        int row = idx >> 3, q = idx & 7;
        unsigned dst = bb + (unsigned)(row * 128 + ((q ^ (row & 7)) * 16));
        const __nv_bfloat16* src = g_wb + (size_t)(i0 + row) * HDIM + kt + q * 8;
        asm volatile("cp.async.cg.shared.global [%0], [%1], 16;"
                     :: "r"(dst), "l"(src) : "memory");
    }
    asm volatile("cp.async.commit_group;" ::: "memory");
}

// ---------------------------------------------------------------------------
// Convert kernels (fp32 -> bf16, RTN)
// ---------------------------------------------------------------------------
__global__ void convert_enc_kernel(const float* __restrict__ enc) {
    size_t gid = (size_t)blockIdx.x * blockDim.x + threadIdx.x;
    size_t base = gid * 8;
    float4 a = *(const float4*)(enc + base);
    float4 b = *(const float4*)(enc + base + 4);
    __nv_bfloat162 r[4];
    r[0] = __floats2bfloat162_rn(a.x, a.y);
    r[1] = __floats2bfloat162_rn(a.z, a.w);
    r[2] = __floats2bfloat162_rn(b.x, b.y);
    r[3] = __floats2bfloat162_rn(b.z, b.w);
    *(uint4*)(g_encb + base) = *(uint4*)r;
}
__global__ void convert_w_kernel(const float* __restrict__ attn_w) {
    size_t gid = (size_t)blockIdx.x * blockDim.x + threadIdx.x;
    size_t base = gid * 8;
    size_t i = base >> 10, k = base & 1023;
    const float* src = attn_w + i * H3 + 2 * HDIM + k;
    float4 a = *(const float4*)src;
    float4 b = *(const float4*)(src + 4);
    __nv_bfloat162 r[4];
    r[0] = __floats2bfloat162_rn(a.x, a.y);
    r[1] = __floats2bfloat162_rn(a.z, a.w);
    r[2] = __floats2bfloat162_rn(b.x, b.y);
    r[3] = __floats2bfloat162_rn(b.z, b.w);
    *(uint4*)(g_wb + base) = *(uint4*)r;
}

// ---------------------------------------------------------------------------
// Kernel 1: c[i] = hidden . attn_w[i, 0:2H] + attn_b[i]   (fp32)
// ---------------------------------------------------------------------------
__global__ void precompute_c_kernel(const float* __restrict__ hidden,
                                    const float* __restrict__ attn_w,
                                    const float* __restrict__ attn_b) {
    int warp = (blockIdx.x * blockDim.x + threadIdx.x) >> 5;
    int lane = threadIdx.x & 31;
    if (warp >= HDIM) return;
    const float* wrow = attn_w + (size_t)warp * H3;
    float s = 0.f;
    #pragma unroll 8
    for (int j = lane; j < 2 * HDIM; j += 32)
        s += hidden[j] * wrow[j];
    #pragma unroll
    for (int off = 16; off; off >>= 1)
        s += __shfl_down_sync(0xffffffffu, s, off);
    if (lane == 0) g_c[warp] = s + attn_b[warp];
}

// ---------------------------------------------------------------------------
// Kernel 2: bf16 m16n8k16 GEMM + fused tanh / v-dot / exp epilogue.
//   4 warps = 2(M) x 2(N).  Warp tile 64x64 (mt=4, nt=8).  acc = 128 regs.
//   255-reg budget (launch_bounds 128,2).  128 MMA + 32 LDSM per warp-chunk.
// ---------------------------------------------------------------------------
__global__ __launch_bounds__(NTHR, 2)
void attn_main_kernel(const float* __restrict__ v_w, float* __restrict__ out) {
    extern __shared__ char smem[];
    const unsigned sb = smem_u32(smem);
    const int tid  = threadIdx.x;
    const int wid  = tid >> 5;
    const int lane = tid & 31;
    const int g    = lane >> 2;        // 0..7
    const int c    = lane & 3;         // 0..3
    const int m0   = (wid & 1) * 64;   // 2 M-warps
    const int n0   = (wid >> 1) * 64;  // 2 N-warps
    const int s0   = blockIdx.x * BM;

    float* red = (float*)(smem + SM_RED);
    float* sr  = (float*)(smem + SM_SR);

    // ldmatrix lane geometry (rows fixed per lane; 16B column unit swizzled)
    const int arow  = m0 + ((lane >> 3) & 1) * 8 + (lane & 7); // + mt*16
    const int aswz  = arow & 7;
    const int acol  = lane >> 4;                               // 0..1 (k half)
    const int brow  = n0 + (lane >> 4) * 8 + (lane & 7);       // + p*16
    const int bswz  = brow & 7;
    const int bcol  = (lane >> 3) & 1;                         // 0..1 (k half)

    load_chunk(sb, 0, 0, s0, tid);
    load_chunk(sb, 1, 1, s0, tid);

    float acc[4][8][4];
    float part[8];
    #pragma unroll
    for (int r = 0; r < 8; r++) part[r] = 0.f;

    for (int gc = 0; gc < NCHUNKS; gc++) {
        const int stage = gc % NSTAGE;
        if (gc < NCHUNKS - 1)
            asm volatile("cp.async.wait_group 1;" ::: "memory");
        else
            asm volatile("cp.async.wait_group 0;" ::: "memory");
        __syncthreads();

        if (gc + 2 < NCHUNKS)
            load_chunk(sb, (gc + 2) % NSTAGE, gc + 2, s0, tid);

        if ((gc & (CH_PER_PASS - 1)) == 0) {
            #pragma unroll
            for (int mt = 0; mt < 4; mt++)
                #pragma unroll
                for (int nt = 0; nt < 8; nt++)
                    #pragma unroll
                    for (int q = 0; q < 4; q++) acc[mt][nt][q] = 0.f;
        }

        const unsigned aS = sb + SM_A + stage * STG;
        const unsigned bS = sb + SM_B + stage * STG;

        #pragma unroll
        for (int ks = 0; ks < 4; ks++) {       // four k16 steps cover KCH=64
            uint32_t af[4][4], bf[4][4];
            const int aq = ((ks * 2 + acol) ^ aswz) * 16;
            const int bq = ((ks * 2 + bcol) ^ bswz) * 16;
            #pragma unroll
            for (int mt = 0; mt < 4; mt++)
                ldsm4(af[mt], aS + (unsigned)((arow + mt * 16) * 128 + aq));
            #pragma unroll
            for (int p = 0; p < 4; p++)
                ldsm4(bf[p], bS + (unsigned)((brow + p * 16) * 128 + bq));
            #pragma unroll
            for (int p = 0; p < 4; p++) {
                #pragma unroll
                for (int mt = 0; mt < 4; mt++) {
                    mma16(acc[mt][2 * p + 0], af[mt], bf[p][0], bf[p][1]);
                    mma16(acc[mt][2 * p + 1], af[mt], bf[p][2], bf[p][3]);
                }
            }
        }

        // per-pass fused epilogue: tanh + v-dot into register partials
        if ((gc & (CH_PER_PASS - 1)) == CH_PER_PASS - 1) {
            const int pass = gc / CH_PER_PASS;
            #pragma unroll
            for (int mt = 0; mt < 4; mt++) {
                #pragma unroll
                for (int nt = 0; nt < 8; nt++) {
                    int i = pass * BN + n0 + nt * 8 + c * 2;
                    float2 cv = __ldg((const float2*)(g_c + i));
                    float2 vv = __ldg((const float2*)(v_w + i));
                    part[mt*2+0] = fmaf(vv.x, fast_tanh(acc[mt][nt][0] + cv.x),
                                   fmaf(vv.y, fast_tanh(acc[mt][nt][1] + cv.y),
                                        part[mt*2+0]));
                    part[mt*2+1] = fmaf(vv.x, fast_tanh(acc[mt][nt][2] + cv.x),
                                   fmaf(vv.y, fast_tanh(acc[mt][nt][3] + cv.y),
                                        part[mt*2+1]));
                }
            }
        }
    }

    // reduce the 4 quad lanes (same rows, different col pairs)
    #pragma unroll
    for (int r = 0; r < 8; r++) {
        part[r] += __shfl_xor_sync(0xffffffffu, part[r], 1);
        part[r] += __shfl_xor_sync(0xffffffffu, part[r], 2);
    }
    if (c == 0) {
        const int nw = wid >> 1;
        #pragma unroll
        for (int mt = 0; mt < 4; mt++) {
            #pragma unroll
            for (int h = 0; h < 2; h++) {
                int row = m0 + mt * 16 + h * 8 + g;
                red[nw * 128 + row] = part[mt * 2 + h];
            }
        }
    }
    __syncthreads();

    // logits -> exp -> output + deterministic block partial
    float logit = red[tid] + red[128 + tid];   // |logit| <= ~26
    float ex = expf(logit);
    out[s0 + tid] = ex;
    float wsum = ex;
    #pragma unroll
    for (int off = 16; off; off >>= 1)
        wsum += __shfl_down_sync(0xffffffffu, wsum, off);
    if (lane == 0) sr[wid] = wsum;
    __syncthreads();
    if (tid == 0)
        g_part[blockIdx.x] = sr[0] + sr[1] + sr[2] + sr[3];
}

// ---------------------------------------------------------------------------
// Kernel 3: finalize — every block redundantly tree-reduces the 256 block
// partials (deterministic), then normalizes its slice of out.
// ---------------------------------------------------------------------------
__global__ void finalize_kernel(float* __restrict__ out) {
    __shared__ float sm[GRID_MAIN];
    int t = threadIdx.x;
    sm[t] = g_part[t];
    __syncthreads();
    #pragma unroll
    for (int o = GRID_MAIN / 2; o > 0; o >>= 1) {
        if (t < o) sm[t] += sm[t + o];
        __syncthreads();
    }
    float inv = 1.f / sm[0];
    int i = blockIdx.x * 256 + t;
    out[i] *= inv;
}

// ---------------------------------------------------------------------------
extern "C" void kernel_launch(void* const* d_in, const int* in_sizes, int n_in,
                              void* d_out, int out_size) {
    const float* hidden = (const float*)d_in[0];
    const float* enc    = (const float*)d_in[1];
    const float* attn_w = (const float*)d_in[2];
    const float* attn_b = (const float*)d_in[3];
    const float* v_w    = (const float*)d_in[4];
    float* out = (float*)d_out;

    cudaFuncSetAttribute(attn_main_kernel,
                         cudaFuncAttributeMaxDynamicSharedMemorySize, SMEM_TOTAL);

    convert_enc_kernel<<<16384, 256>>>(enc);
    convert_w_kernel<<<512, 256>>>(attn_w);
    precompute_c_kernel<<<128, 256>>>(hidden, attn_w, attn_b);
    attn_main_kernel<<<GRID_MAIN, NTHR, SMEM_TOTAL>>>(v_w, out);
    finalize_kernel<<<S_LEN / 256, 256>>>(out);
}

// round 13
// speedup vs baseline: 1.1575x; 1.0078x over previous
#include <cuda_runtime.h>
#include <cuda_bf16.h>
#include <cstdint>

#define S_LEN 32768
#define HDIM  1024
#define H3    3072
#define BM    128                 // s-rows per CTA
#define BN    128                 // i-cols per pass
#define NPASS 8
#define KCH   64                  // k elements per chunk (128 B bf16 row)
#define CH_PER_PASS (HDIM / KCH)  // 16
#define NCHUNKS (NPASS * CH_PER_PASS)   // 128
#define GRID_MAIN (S_LEN / BM)    // 256
#define NTHR  128
#define NSTAGE 3

// SMEM (bytes). Rows exactly 128 B, XOR-swizzled (SW128).
#define STG    16384              // 128 rows * 128 B
#define SM_A   0                  // 3 stages
#define SM_B   (NSTAGE * STG)                // 49152, 3 stages
#define SM_RED (SM_B + NSTAGE * STG)         // 98304 (256 floats)
#define SM_SR  (SM_RED + 1024)               // 99328
#define SMEM_TOTAL (SM_SR + 16)              // 99344 (x2 CTA/SM = 199 KB)

__device__ float g_c[HDIM];
__device__ float g_part[GRID_MAIN];
__device__ __align__(16) __nv_bfloat16 g_encb[(size_t)S_LEN * HDIM]; // 64 MB
__device__ __align__(16) __nv_bfloat16 g_wb[HDIM * HDIM];            // 2 MB

// ---------------- helpers ----------------
__device__ __forceinline__ unsigned smem_u32(const void* p) {
    return (unsigned)__cvta_generic_to_shared(p);
}
__device__ __forceinline__ float fast_tanh(float x) {
    float e, r;
    asm("ex2.approx.f32 %0, %1;" : "=f"(e) : "f"(x * 2.885390082f));
    asm("rcp.approx.f32 %0, %1;" : "=f"(r) : "f"(e + 1.0f));
    return fmaf(-2.0f, r, 1.0f);
}
__device__ __forceinline__ void mma16(float* d, const uint32_t* a,
                                      uint32_t b0, uint32_t b1) {
    asm volatile(
        "mma.sync.aligned.m16n8k16.row.col.f32.bf16.bf16.f32 "
        "{%0,%1,%2,%3}, {%4,%5,%6,%7}, {%8,%9}, {%0,%1,%2,%3};"
        : "+f"(d[0]), "+f"(d[1]), "+f"(d[2]), "+f"(d[3])
        : "r"(a[0]), "r"(a[1]), "r"(a[2]), "r"(a[3]), "r"(b0), "r"(b1));
}
__device__ __forceinline__ void ldsm4(uint32_t* d, unsigned addr) {
    asm volatile(
        "ldmatrix.sync.aligned.m8n8.x4.shared.b16 {%0,%1,%2,%3}, [%4];"
        : "=r"(d[0]), "=r"(d[1]), "=r"(d[2]), "=r"(d[3]) : "r"(addr));
}

// cp.async one chunk: A 128x64 bf16, B 128x64 bf16, SW128 XOR swizzle
__device__ __forceinline__ void load_chunk(unsigned sb, int stage, int gc,
                                           int s0, int tid) {
    const int kt = (gc & (CH_PER_PASS - 1)) * KCH;
    const int i0 = (gc / CH_PER_PASS) * BN;
    const unsigned ab = sb + SM_A + stage * STG;
    const unsigned bb = sb + SM_B + stage * STG;
    #pragma unroll
    for (int j = 0; j < 8; j++) {              // A: 1024 x 16B
        int idx = tid + j * NTHR;
        int row = idx >> 3, q = idx & 7;
        unsigned dst = ab + (unsigned)(row * 128 + ((q ^ (row & 7)) * 16));
        const __nv_bfloat16* src = g_encb + (size_t)(s0 + row) * HDIM + kt + q * 8;
        asm volatile("cp.async.cg.shared.global [%0], [%1], 16;"
                     :: "r"(dst), "l"(src) : "memory");
    }
    #pragma unroll
    for (int j = 0; j < 8; j++) {              // B: 1024 x 16B
        int idx = tid + j * NTHR;
        int row = idx >> 3, q = idx & 7;
        unsigned dst = bb + (unsigned)(row * 128 + ((q ^ (row & 7)) * 16));
        const __nv_bfloat16* src = g_wb + (size_t)(i0 + row) * HDIM + kt + q * 8;
        asm volatile("cp.async.cg.shared.global [%0], [%1], 16;"
                     :: "r"(dst), "l"(src) : "memory");
    }
    asm volatile("cp.async.commit_group;" ::: "memory");
}

// ---------------------------------------------------------------------------
// Convert kernels (fp32 -> bf16, RTN)
// ---------------------------------------------------------------------------
__global__ void convert_enc_kernel(const float* __restrict__ enc) {
    size_t gid = (size_t)blockIdx.x * blockDim.x + threadIdx.x;
    size_t base = gid * 8;
    float4 a = *(const float4*)(enc + base);
    float4 b = *(const float4*)(enc + base + 4);
    __nv_bfloat162 r[4];
    r[0] = __floats2bfloat162_rn(a.x, a.y);
    r[1] = __floats2bfloat162_rn(a.z, a.w);
    r[2] = __floats2bfloat162_rn(b.x, b.y);
    r[3] = __floats2bfloat162_rn(b.z, b.w);
    *(uint4*)(g_encb + base) = *(uint4*)r;
}
__global__ void convert_w_kernel(const float* __restrict__ attn_w) {
    size_t gid = (size_t)blockIdx.x * blockDim.x + threadIdx.x;
    size_t base = gid * 8;
    size_t i = base >> 10, k = base & 1023;
    const float* src = attn_w + i * H3 + 2 * HDIM + k;
    float4 a = *(const float4*)src;
    float4 b = *(const float4*)(src + 4);
    __nv_bfloat162 r[4];
    r[0] = __floats2bfloat162_rn(a.x, a.y);
    r[1] = __floats2bfloat162_rn(a.z, a.w);
    r[2] = __floats2bfloat162_rn(b.x, b.y);
    r[3] = __floats2bfloat162_rn(b.z, b.w);
    *(uint4*)(g_wb + base) = *(uint4*)r;
}

// ---------------------------------------------------------------------------
// Kernel 1: c[i] = hidden . attn_w[i, 0:2H] + attn_b[i]   (fp32)
// ---------------------------------------------------------------------------
__global__ void precompute_c_kernel(const float* __restrict__ hidden,
                                    const float* __restrict__ attn_w,
                                    const float* __restrict__ attn_b) {
    int warp = (blockIdx.x * blockDim.x + threadIdx.x) >> 5;
    int lane = threadIdx.x & 31;
    if (warp >= HDIM) return;
    const float* wrow = attn_w + (size_t)warp * H3;
    float s = 0.f;
    #pragma unroll 8
    for (int j = lane; j < 2 * HDIM; j += 32)
        s += hidden[j] * wrow[j];
    #pragma unroll
    for (int off = 16; off; off >>= 1)
        s += __shfl_down_sync(0xffffffffu, s, off);
    if (lane == 0) g_c[warp] = s + attn_b[warp];
}

// ---------------------------------------------------------------------------
// Kernel 2: bf16 m16n8k16 GEMM + fused tanh / v-dot / exp epilogue.
//   4 warps = 2(M) x 2(N).  Warp tile 64x64 (mt=4, nt=8).  acc = 128 regs.
//   255-reg budget: ks-level fragment ping-pong (LDSM ks+1 ahead of MMA ks).
// ---------------------------------------------------------------------------
__global__ __launch_bounds__(NTHR, 2)
void attn_main_kernel(const float* __restrict__ v_w, float* __restrict__ out) {
    extern __shared__ char smem[];
    const unsigned sb = smem_u32(smem);
    const int tid  = threadIdx.x;
    const int wid  = tid >> 5;
    const int lane = tid & 31;
    const int g    = lane >> 2;        // 0..7
    const int c    = lane & 3;         // 0..3
    const int m0   = (wid & 1) * 64;   // 2 M-warps
    const int n0   = (wid >> 1) * 64;  // 2 N-warps
    const int s0   = blockIdx.x * BM;

    float* red = (float*)(smem + SM_RED);
    float* sr  = (float*)(smem + SM_SR);

    // ldmatrix lane geometry (rows fixed per lane; 16B column unit swizzled)
    const int arow  = m0 + ((lane >> 3) & 1) * 8 + (lane & 7); // + mt*16
    const int aswz  = arow & 7;
    const int acol  = lane >> 4;                               // 0..1 (k half)
    const int brow  = n0 + (lane >> 4) * 8 + (lane & 7);       // + p*16
    const int bswz  = brow & 7;
    const int bcol  = (lane >> 3) & 1;                         // 0..1 (k half)

    load_chunk(sb, 0, 0, s0, tid);
    load_chunk(sb, 1, 1, s0, tid);

    float acc[4][8][4];
    float part[8];
    #pragma unroll
    for (int r = 0; r < 8; r++) part[r] = 0.f;

    for (int gc = 0; gc < NCHUNKS; gc++) {
        const int stage = gc % NSTAGE;
        if (gc < NCHUNKS - 1)
            asm volatile("cp.async.wait_group 1;" ::: "memory");
        else
            asm volatile("cp.async.wait_group 0;" ::: "memory");
        __syncthreads();

        if (gc + 2 < NCHUNKS)
            load_chunk(sb, (gc + 2) % NSTAGE, gc + 2, s0, tid);

        if ((gc & (CH_PER_PASS - 1)) == 0) {
            #pragma unroll
            for (int mt = 0; mt < 4; mt++)
                #pragma unroll
                for (int nt = 0; nt < 8; nt++)
                    #pragma unroll
                    for (int q = 0; q < 4; q++) acc[mt][nt][q] = 0.f;
        }

        const unsigned aS = sb + SM_A + stage * STG;
        const unsigned bS = sb + SM_B + stage * STG;

        // ---- ks-pipelined inner loop: LDSM(ks+1) issued before MMA(ks) ----
        uint32_t af[2][4][4], bf[2][4][4];
        {
            const int aq = (acol ^ aswz) * 16;            // ks = 0
            const int bq = (bcol ^ bswz) * 16;
            #pragma unroll
            for (int mt = 0; mt < 4; mt++)
                ldsm4(af[0][mt], aS + (unsigned)((arow + mt * 16) * 128 + aq));
            #pragma unroll
            for (int p = 0; p < 4; p++)
                ldsm4(bf[0][p], bS + (unsigned)((brow + p * 16) * 128 + bq));
        }
        #pragma unroll
        for (int ks = 0; ks < 4; ks++) {
            const int cur = ks & 1, nxt = cur ^ 1;
            if (ks < 3) {
                const int aq = (((ks + 1) * 2 + acol) ^ aswz) * 16;
                const int bq = (((ks + 1) * 2 + bcol) ^ bswz) * 16;
                #pragma unroll
                for (int mt = 0; mt < 4; mt++)
                    ldsm4(af[nxt][mt], aS + (unsigned)((arow + mt * 16) * 128 + aq));
                #pragma unroll
                for (int p = 0; p < 4; p++)
                    ldsm4(bf[nxt][p], bS + (unsigned)((brow + p * 16) * 128 + bq));
            }
            #pragma unroll
            for (int p = 0; p < 4; p++) {
                #pragma unroll
                for (int mt = 0; mt < 4; mt++) {
                    mma16(acc[mt][2 * p + 0], af[cur][mt], bf[cur][p][0], bf[cur][p][1]);
                    mma16(acc[mt][2 * p + 1], af[cur][mt], bf[cur][p][2], bf[cur][p][3]);
                }
            }
        }

        // per-pass fused epilogue: tanh + v-dot into register partials
        if ((gc & (CH_PER_PASS - 1)) == CH_PER_PASS - 1) {
            const int pass = gc / CH_PER_PASS;
            #pragma unroll
            for (int mt = 0; mt < 4; mt++) {
                #pragma unroll
                for (int nt = 0; nt < 8; nt++) {
                    int i = pass * BN + n0 + nt * 8 + c * 2;
                    float2 cv = __ldg((const float2*)(g_c + i));
                    float2 vv = __ldg((const float2*)(v_w + i));
                    part[mt*2+0] = fmaf(vv.x, fast_tanh(acc[mt][nt][0] + cv.x),
                                   fmaf(vv.y, fast_tanh(acc[mt][nt][1] + cv.y),
                                        part[mt*2+0]));
                    part[mt*2+1] = fmaf(vv.x, fast_tanh(acc[mt][nt][2] + cv.x),
                                   fmaf(vv.y, fast_tanh(acc[mt][nt][3] + cv.y),
                                        part[mt*2+1]));
                }
            }
        }
    }

    // reduce the 4 quad lanes (same rows, different col pairs)
    #pragma unroll
    for (int r = 0; r < 8; r++) {
        part[r] += __shfl_xor_sync(0xffffffffu, part[r], 1);
        part[r] += __shfl_xor_sync(0xffffffffu, part[r], 2);
    }
    if (c == 0) {
        const int nw = wid >> 1;
        #pragma unroll
        for (int mt = 0; mt < 4; mt++) {
            #pragma unroll
            for (int h = 0; h < 2; h++) {
                int row = m0 + mt * 16 + h * 8 + g;
                red[nw * 128 + row] = part[mt * 2 + h];
            }
        }
    }
    __syncthreads();

    // logits -> exp -> output + deterministic block partial
    float logit = red[tid] + red[128 + tid];   // |logit| <= ~26
    float ex = expf(logit);
    out[s0 + tid] = ex;
    float wsum = ex;
    #pragma unroll
    for (int off = 16; off; off >>= 1)
        wsum += __shfl_down_sync(0xffffffffu, wsum, off);
    if (lane == 0) sr[wid] = wsum;
    __syncthreads();
    if (tid == 0)
        g_part[blockIdx.x] = sr[0] + sr[1] + sr[2] + sr[3];
}

// ---------------------------------------------------------------------------
// Kernel 3: finalize — every block redundantly tree-reduces the 256 block
// partials (deterministic), then normalizes its slice of out.
// ---------------------------------------------------------------------------
__global__ void finalize_kernel(float* __restrict__ out) {
    __shared__ float sm[GRID_MAIN];
    int t = threadIdx.x;
    sm[t] = g_part[t];
    __syncthreads();
    #pragma unroll
    for (int o = GRID_MAIN / 2; o > 0; o >>= 1) {
        if (t < o) sm[t] += sm[t + o];
        __syncthreads();
    }
    float inv = 1.f / sm[0];
    int i = blockIdx.x * 256 + t;
    out[i] *= inv;
}

// ---------------------------------------------------------------------------
extern "C" void kernel_launch(void* const* d_in, const int* in_sizes, int n_in,
                              void* d_out, int out_size) {
    const float* hidden = (const float*)d_in[0];
    const float* enc    = (const float*)d_in[1];
    const float* attn_w = (const float*)d_in[2];
    const float* attn_b = (const float*)d_in[3];
    const float* v_w    = (const float*)d_in[4];
    float* out = (float*)d_out;

    cudaFuncSetAttribute(attn_main_kernel,
                         cudaFuncAttributeMaxDynamicSharedMemorySize, SMEM_TOTAL);

    convert_enc_kernel<<<16384, 256>>>(enc);
    convert_w_kernel<<<512, 256>>>(attn_w);
    precompute_c_kernel<<<128, 256>>>(hidden, attn_w, attn_b);
    attn_main_kernel<<<GRID_MAIN, NTHR, SMEM_TOTAL>>>(v_w, out);
    finalize_kernel<<<S_LEN / 256, 256>>>(out);
}

// round 14
// speedup vs baseline: 1.2764x; 1.1027x over previous
#include <cuda_runtime.h>
#include <cuda_bf16.h>
#include <cstdint>

#define S_LEN 32768
#define HDIM  1024
#define H3    3072
#define BM    128                 // s-rows per unit
#define BN    128                 // i-cols per unit (one pass)
#define NPASS 8
#define KCH   64                  // k elements per chunk (128 B bf16 row)
#define CH_PER_UNIT (HDIM / KCH)  // 16
#define NTILES (S_LEN / BM)       // 256
#define NUNITS (NTILES * NPASS)   // 2048
#define GRID_MAIN 296             // 2 CTAs x 148 SMs, persistent
#define NTHR  128
#define NSTAGE 3

// SMEM (bytes). Rows exactly 128 B, XOR-swizzled (SW128).
#define STG    16384              // 128 rows * 128 B
#define SM_A   0                  // 3 stages
#define SM_B   (NSTAGE * STG)                // 49152, 3 stages
#define SM_RED (SM_B + NSTAGE * STG)         // 98304 (256 floats)
#define SMEM_TOTAL (SM_RED + 1024 + 16)      // 99344 (x2 CTA/SM = 199 KB)

__device__ float g_c[HDIM];
__device__ float g_lp[NPASS * S_LEN];        // per-pass logit partials (1 MB)
__device__ float g_part[S_LEN / 256];        // 128 exp block sums
__device__ __align__(16) __nv_bfloat16 g_encb[(size_t)S_LEN * HDIM]; // 64 MB
__device__ __align__(16) __nv_bfloat16 g_wb[HDIM * HDIM];            // 2 MB

// ---------------- helpers ----------------
__device__ __forceinline__ unsigned smem_u32(const void* p) {
    return (unsigned)__cvta_generic_to_shared(p);
}
__device__ __forceinline__ float fast_tanh(float x) {
    float e, r;
    asm("ex2.approx.f32 %0, %1;" : "=f"(e) : "f"(x * 2.885390082f));
    asm("rcp.approx.f32 %0, %1;" : "=f"(r) : "f"(e + 1.0f));
    return fmaf(-2.0f, r, 1.0f);
}
__device__ __forceinline__ void mma16(float* d, const uint32_t* a,
                                      uint32_t b0, uint32_t b1) {
    asm volatile(
        "mma.sync.aligned.m16n8k16.row.col.f32.bf16.bf16.f32 "
        "{%0,%1,%2,%3}, {%4,%5,%6,%7}, {%8,%9}, {%0,%1,%2,%3};"
        : "+f"(d[0]), "+f"(d[1]), "+f"(d[2]), "+f"(d[3])
        : "r"(a[0]), "r"(a[1]), "r"(a[2]), "r"(a[3]), "r"(b0), "r"(b1));
}
__device__ __forceinline__ void ldsm4(uint32_t* d, unsigned addr) {
    asm volatile(
        "ldmatrix.sync.aligned.m8n8.x4.shared.b16 {%0,%1,%2,%3}, [%4];"
        : "=r"(d[0]), "=r"(d[1]), "=r"(d[2]), "=r"(d[3]) : "r"(addr));
}

// cp.async one chunk of a unit: A 128x64 bf16, B 128x64 bf16 (SW128 swizzle)
__device__ __forceinline__ void load_chunk(unsigned sb, int stage, int ch,
                                           int s0, int i0, int tid) {
    const int kt = ch * KCH;
    const unsigned ab = sb + SM_A + stage * STG;
    const unsigned bb = sb + SM_B + stage * STG;
    #pragma unroll
    for (int j = 0; j < 8; j++) {              // A: 1024 x 16B
        int idx = tid + j * NTHR;
        int row = idx >> 3, q = idx & 7;
        unsigned dst = ab + (unsigned)(row * 128 + ((q ^ (row & 7)) * 16));
        const __nv_bfloat16* src = g_encb + (size_t)(s0 + row) * HDIM + kt + q * 8;
        asm volatile("cp.async.cg.shared.global [%0], [%1], 16;"
                     :: "r"(dst), "l"(src) : "memory");
    }
    #pragma unroll
    for (int j = 0; j < 8; j++) {              // B: 1024 x 16B
        int idx = tid + j * NTHR;
        int row = idx >> 3, q = idx & 7;
        unsigned dst = bb + (unsigned)(row * 128 + ((q ^ (row & 7)) * 16));
        const __nv_bfloat16* src = g_wb + (size_t)(i0 + row) * HDIM + kt + q * 8;
        asm volatile("cp.async.cg.shared.global [%0], [%1], 16;"
                     :: "r"(dst), "l"(src) : "memory");
    }
    asm volatile("cp.async.commit_group;" ::: "memory");
}

// ---------------------------------------------------------------------------
// Convert kernels (fp32 -> bf16, RTN)
// ---------------------------------------------------------------------------
__global__ void convert_enc_kernel(const float* __restrict__ enc) {
    size_t gid = (size_t)blockIdx.x * blockDim.x + threadIdx.x;
    size_t base = gid * 8;
    float4 a = *(const float4*)(enc + base);
    float4 b = *(const float4*)(enc + base + 4);
    __nv_bfloat162 r[4];
    r[0] = __floats2bfloat162_rn(a.x, a.y);
    r[1] = __floats2bfloat162_rn(a.z, a.w);
    r[2] = __floats2bfloat162_rn(b.x, b.y);
    r[3] = __floats2bfloat162_rn(b.z, b.w);
    *(uint4*)(g_encb + base) = *(uint4*)r;
}
__global__ void convert_w_kernel(const float* __restrict__ attn_w) {
    size_t gid = (size_t)blockIdx.x * blockDim.x + threadIdx.x;
    size_t base = gid * 8;
    size_t i = base >> 10, k = base & 1023;
    const float* src = attn_w + i * H3 + 2 * HDIM + k;
    float4 a = *(const float4*)src;
    float4 b = *(const float4*)(src + 4);
    __nv_bfloat162 r[4];
    r[0] = __floats2bfloat162_rn(a.x, a.y);
    r[1] = __floats2bfloat162_rn(a.z, a.w);
    r[2] = __floats2bfloat162_rn(b.x, b.y);
    r[3] = __floats2bfloat162_rn(b.z, b.w);
    *(uint4*)(g_wb + base) = *(uint4*)r;
}

// ---------------------------------------------------------------------------
// Kernel 1: c[i] = hidden . attn_w[i, 0:2H] + attn_b[i]   (fp32)
// ---------------------------------------------------------------------------
__global__ void precompute_c_kernel(const float* __restrict__ hidden,
                                    const float* __restrict__ attn_w,
                                    const float* __restrict__ attn_b) {
    int warp = (blockIdx.x * blockDim.x + threadIdx.x) >> 5;
    int lane = threadIdx.x & 31;
    if (warp >= HDIM) return;
    const float* wrow = attn_w + (size_t)warp * H3;
    float s = 0.f;
    #pragma unroll 8
    for (int j = lane; j < 2 * HDIM; j += 32)
        s += hidden[j] * wrow[j];
    #pragma unroll
    for (int off = 16; off; off >>= 1)
        s += __shfl_down_sync(0xffffffffu, s, off);
    if (lane == 0) g_c[warp] = s + attn_b[warp];
}

// ---------------------------------------------------------------------------
// Kernel 2: persistent bf16 m16n8k16 GEMM over 2048 (tile, pass) units.
//   4 warps = 2(M) x 2(N).  Warp tile 64x64 (mt=4, nt=8).  acc = 128 regs.
//   Unit: 16 k-chunks + fused tanh/v-dot epilogue -> g_lp[pass][s].
// ---------------------------------------------------------------------------
__global__ __launch_bounds__(NTHR, 2)
void attn_main_kernel(const float* __restrict__ v_w) {
    extern __shared__ char smem[];
    const unsigned sb = smem_u32(smem);
    const int tid  = threadIdx.x;
    const int wid  = tid >> 5;
    const int lane = tid & 31;
    const int g    = lane >> 2;        // 0..7
    const int c    = lane & 3;         // 0..3
    const int m0   = (wid & 1) * 64;   // 2 M-warps
    const int n0   = (wid >> 1) * 64;  // 2 N-warps

    float* red = (float*)(smem + SM_RED);

    // ldmatrix lane geometry (rows fixed per lane; 16B column unit swizzled)
    const int arow  = m0 + ((lane >> 3) & 1) * 8 + (lane & 7); // + mt*16
    const int aswz  = arow & 7;
    const int acol  = lane >> 4;                               // 0..1 (k half)
    const int brow  = n0 + (lane >> 4) * 8 + (lane & 7);       // + p*16
    const int bswz  = brow & 7;
    const int bcol  = (lane >> 3) & 1;                         // 0..1 (k half)

    for (int u = blockIdx.x; u < NUNITS; u += GRID_MAIN) {
        const int tile = u >> 3;
        const int pass = u & 7;
        const int s0   = tile * BM;
        const int i0   = pass * BN;

        // unit prologue: chunks 0, 1 into stages 0, 1
        load_chunk(sb, 0, 0, s0, i0, tid);
        load_chunk(sb, 1, 1, s0, i0, tid);

        float acc[4][8][4];
        #pragma unroll
        for (int mt = 0; mt < 4; mt++)
            #pragma unroll
            for (int nt = 0; nt < 8; nt++)
                #pragma unroll
                for (int q = 0; q < 4; q++) acc[mt][nt][q] = 0.f;

        for (int ch = 0; ch < CH_PER_UNIT; ch++) {
            const int stage = ch % NSTAGE;
            if (ch < CH_PER_UNIT - 1)
                asm volatile("cp.async.wait_group 1;" ::: "memory");
            else
                asm volatile("cp.async.wait_group 0;" ::: "memory");
            __syncthreads();

            if (ch + 2 < CH_PER_UNIT)
                load_chunk(sb, (ch + 2) % NSTAGE, ch + 2, s0, i0, tid);

            const unsigned aS = sb + SM_A + stage * STG;
            const unsigned bS = sb + SM_B + stage * STG;

            #pragma unroll
            for (int ks = 0; ks < 4; ks++) {   // four k16 steps cover KCH=64
                uint32_t af[4][4], bf[4][4];
                const int aq = ((ks * 2 + acol) ^ aswz) * 16;
                const int bq = ((ks * 2 + bcol) ^ bswz) * 16;
                #pragma unroll
                for (int mt = 0; mt < 4; mt++)
                    ldsm4(af[mt], aS + (unsigned)((arow + mt * 16) * 128 + aq));
                #pragma unroll
                for (int p = 0; p < 4; p++)
                    ldsm4(bf[p], bS + (unsigned)((brow + p * 16) * 128 + bq));
                #pragma unroll
                for (int p = 0; p < 4; p++) {
                    #pragma unroll
                    for (int mt = 0; mt < 4; mt++) {
                        mma16(acc[mt][2 * p + 0], af[mt], bf[p][0], bf[p][1]);
                        mma16(acc[mt][2 * p + 1], af[mt], bf[p][2], bf[p][3]);
                    }
                }
            }
        }

        // unit epilogue: tanh + v-dot -> per-thread partials
        float part[8];
        #pragma unroll
        for (int r = 0; r < 8; r++) part[r] = 0.f;
        #pragma unroll
        for (int mt = 0; mt < 4; mt++) {
            #pragma unroll
            for (int nt = 0; nt < 8; nt++) {
                int i = i0 + n0 + nt * 8 + c * 2;
                float2 cv = __ldg((const float2*)(g_c + i));
                float2 vv = __ldg((const float2*)(v_w + i));
                part[mt*2+0] = fmaf(vv.x, fast_tanh(acc[mt][nt][0] + cv.x),
                               fmaf(vv.y, fast_tanh(acc[mt][nt][1] + cv.y),
                                    part[mt*2+0]));
                part[mt*2+1] = fmaf(vv.x, fast_tanh(acc[mt][nt][2] + cv.x),
                               fmaf(vv.y, fast_tanh(acc[mt][nt][3] + cv.y),
                                    part[mt*2+1]));
            }
        }
        #pragma unroll
        for (int r = 0; r < 8; r++) {
            part[r] += __shfl_xor_sync(0xffffffffu, part[r], 1);
            part[r] += __shfl_xor_sync(0xffffffffu, part[r], 2);
        }
        if (c == 0) {
            const int nw = wid >> 1;
            #pragma unroll
            for (int mt = 0; mt < 4; mt++) {
                #pragma unroll
                for (int h = 0; h < 2; h++) {
                    int row = m0 + mt * 16 + h * 8 + g;
                    red[nw * 128 + row] = part[mt * 2 + h];
                }
            }
        }
        __syncthreads();                       // also fences stage reuse
        g_lp[pass * S_LEN + s0 + tid] = red[tid] + red[128 + tid];
    }
}

// ---------------------------------------------------------------------------
// Kernel 3: logits = sum of 8 pass partials (fixed order), exp, block sums.
// ---------------------------------------------------------------------------
__global__ void exp_kernel(float* __restrict__ out) {
    __shared__ float sr[8];
    int s = blockIdx.x * 256 + threadIdx.x;
    float logit = 0.f;
    #pragma unroll
    for (int p = 0; p < NPASS; p++)
        logit += g_lp[p * S_LEN + s];
    float ex = expf(logit);                    // |logit| <= ~26, unshifted safe
    out[s] = ex;
    float w = ex;
    #pragma unroll
    for (int off = 16; off; off >>= 1)
        w += __shfl_down_sync(0xffffffffu, w, off);
    if ((threadIdx.x & 31) == 0) sr[threadIdx.x >> 5] = w;
    __syncthreads();
    if (threadIdx.x == 0) {
        float t = 0.f;
        #pragma unroll
        for (int y = 0; y < 8; y++) t += sr[y];
        g_part[blockIdx.x] = t;
    }
}

// ---------------------------------------------------------------------------
// Kernel 4: finalize — redundant deterministic reduce of 128 partials, scale.
// ---------------------------------------------------------------------------
__global__ void finalize_kernel(float* __restrict__ out) {
    __shared__ float sm[128];
    int t = threadIdx.x;
    if (t < 128) sm[t] = g_part[t];
    __syncthreads();
    #pragma unroll
    for (int o = 64; o > 0; o >>= 1) {
        if (t < o) sm[t] += sm[t + o];
        __syncthreads();
    }
    float inv = 1.f / sm[0];
    int i = blockIdx.x * 256 + t;
    out[i] *= inv;
}

// ---------------------------------------------------------------------------
extern "C" void kernel_launch(void* const* d_in, const int* in_sizes, int n_in,
                              void* d_out, int out_size) {
    const float* hidden = (const float*)d_in[0];
    const float* enc    = (const float*)d_in[1];
    const float* attn_w = (const float*)d_in[2];
    const float* attn_b = (const float*)d_in[3];
    const float* v_w    = (const float*)d_in[4];
    float* out = (float*)d_out;

    cudaFuncSetAttribute(attn_main_kernel,
                         cudaFuncAttributeMaxDynamicSharedMemorySize, SMEM_TOTAL);

    convert_enc_kernel<<<16384, 256>>>(enc);
    convert_w_kernel<<<512, 256>>>(attn_w);
    precompute_c_kernel<<<128, 256>>>(hidden, attn_w, attn_b);
    attn_main_kernel<<<GRID_MAIN, NTHR, SMEM_TOTAL>>>(v_w);
    exp_kernel<<<S_LEN / 256, 256>>>(out);
    finalize_kernel<<<S_LEN / 256, 256>>>(out);
}